// round 1
// baseline (speedup 1.0000x reference)
#include <cuda_runtime.h>
#include <math.h>
#include <float.h>

// Problem constants
#define Bv 2
#define Nv 2048
#define Cv 1024
#define Hv 16
#define Dv 64
#define BHv (Bv*Hv)        // 32
#define MROWS (Bv*Nv)      // 4096
#define C3 (3*Cv)          // 3072

// Static device scratch (allocation-free rule)
__device__ float g_q[BHv*Nv*Dv];            // 16 MB, [b,h,n,d]
__device__ float g_k[BHv*Nv*Dv];
__device__ float g_v[BHv*Nv*Dv];
__device__ float g_s[(size_t)BHv*Nv*Nv];    // 512 MB scores
__device__ float g_attn[MROWS*Cv];          // 16 MB, [b*n, h*d]

// ---------------- Epilogue functors ----------------
struct EpiQKV {
    float *q, *k, *v;
    __device__ __forceinline__ void operator()(int bz, int m, int n, float val) const {
        int b   = m >> 11;          // /2048
        int tok = m & 2047;
        int which = n >> 10;        // 0=q,1=k,2=v
        int h   = (n & 1023) >> 6;
        int dd  = n & 63;
        float* dst = (which == 0) ? q : ((which == 1) ? k : v);
        dst[(((b*Hv + h)*Nv + tok) << 6) + dd] = val;
    }
};

struct EpiS {
    float* s;
    __device__ __forceinline__ void operator()(int bz, int m, int n, float val) const {
        s[((size_t)bz*Nv + m)*Nv + n] = val;
    }
};

struct EpiPV {
    float* attn;
    __device__ __forceinline__ void operator()(int bz, int m, int n, float val) const {
        int b = bz >> 4;
        int h = bz & 15;
        attn[((size_t)(b*Nv + m))*Cv + h*Dv + n] = val;
    }
};

struct EpiOut {
    float* out;
    const float* bias;
    __device__ __forceinline__ void operator()(int bz, int m, int n, float val) const {
        out[(size_t)m*Cv + n] = val + bias[n];
    }
};

// ---------------- GEMM TN: C = A(MxK,rm) * B(NxK,rm)^T ----------------
template<int BM, int BN, int BK, int TM, int TN, class Epi>
__global__ void __launch_bounds__((BM/TM)*(BN/TN))
gemm_tn(const float* __restrict__ A, const float* __restrict__ B,
        int M, int N, int K, long long sA, long long sB, Epi epi)
{
    __shared__ float As[BK][BM + 4];
    __shared__ float Bs[BK][BN + 4];
    constexpr int THREADS = (BM/TM)*(BN/TN);
    int bz = blockIdx.z;
    A += (long long)bz * sA;
    B += (long long)bz * sB;
    int bm = blockIdx.y * BM;
    int bn = blockIdx.x * BN;
    int tid = threadIdx.x;
    int tcol = tid % (BN/TN);
    int trow = tid / (BN/TN);

    float acc[TM][TN];
    #pragma unroll
    for (int i = 0; i < TM; i++)
        #pragma unroll
        for (int j = 0; j < TN; j++) acc[i][j] = 0.f;

    for (int k0 = 0; k0 < K; k0 += BK) {
        #pragma unroll
        for (int i = tid; i < BM*BK; i += THREADS) {
            int m = i / BK, kk = i % BK;
            As[kk][m] = A[(long long)(bm + m)*K + k0 + kk];
        }
        #pragma unroll
        for (int i = tid; i < BN*BK; i += THREADS) {
            int n = i / BK, kk = i % BK;
            Bs[kk][n] = B[(long long)(bn + n)*K + k0 + kk];
        }
        __syncthreads();
        #pragma unroll
        for (int kk = 0; kk < BK; kk++) {
            float ar[TM], br[TN];
            #pragma unroll
            for (int i = 0; i < TM; i++) ar[i] = As[kk][trow*TM + i];
            #pragma unroll
            for (int j = 0; j < TN; j++) br[j] = Bs[kk][tcol*TN + j];
            #pragma unroll
            for (int i = 0; i < TM; i++)
                #pragma unroll
                for (int j = 0; j < TN; j++)
                    acc[i][j] += ar[i] * br[j];
        }
        __syncthreads();
    }
    #pragma unroll
    for (int i = 0; i < TM; i++)
        #pragma unroll
        for (int j = 0; j < TN; j++)
            epi(bz, bm + trow*TM + i, bn + tcol*TN + j, acc[i][j]);
}

// ---------------- GEMM NN: C = A(MxK,rm) * B(KxN,rm) ----------------
template<int BM, int BN, int BK, int TM, int TN, class Epi>
__global__ void __launch_bounds__((BM/TM)*(BN/TN))
gemm_nn(const float* __restrict__ A, const float* __restrict__ B,
        int M, int N, int K, long long sA, long long sB, Epi epi)
{
    __shared__ float As[BK][BM + 4];
    __shared__ float Bs[BK][BN + 4];
    constexpr int THREADS = (BM/TM)*(BN/TN);
    int bz = blockIdx.z;
    A += (long long)bz * sA;
    B += (long long)bz * sB;
    int bm = blockIdx.y * BM;
    int bn = blockIdx.x * BN;
    int tid = threadIdx.x;
    int tcol = tid % (BN/TN);
    int trow = tid / (BN/TN);

    float acc[TM][TN];
    #pragma unroll
    for (int i = 0; i < TM; i++)
        #pragma unroll
        for (int j = 0; j < TN; j++) acc[i][j] = 0.f;

    for (int k0 = 0; k0 < K; k0 += BK) {
        #pragma unroll
        for (int i = tid; i < BM*BK; i += THREADS) {
            int m = i / BK, kk = i % BK;
            As[kk][m] = A[(long long)(bm + m)*K + k0 + kk];
        }
        #pragma unroll
        for (int i = tid; i < BN*BK; i += THREADS) {
            int kk = i / BN, n = i % BN;
            Bs[kk][n] = B[(long long)(k0 + kk)*N + bn + n];
        }
        __syncthreads();
        #pragma unroll
        for (int kk = 0; kk < BK; kk++) {
            float ar[TM], br[TN];
            #pragma unroll
            for (int i = 0; i < TM; i++) ar[i] = As[kk][trow*TM + i];
            #pragma unroll
            for (int j = 0; j < TN; j++) br[j] = Bs[kk][tcol*TN + j];
            #pragma unroll
            for (int i = 0; i < TM; i++)
                #pragma unroll
                for (int j = 0; j < TN; j++)
                    acc[i][j] += ar[i] * br[j];
        }
        __syncthreads();
    }
    #pragma unroll
    for (int i = 0; i < TM; i++)
        #pragma unroll
        for (int j = 0; j < TN; j++)
            epi(bz, bm + trow*TM + i, bn + tcol*TN + j, acc[i][j]);
}

// ---------------- LayerNorm over d=64, one warp per row ----------------
__global__ void ln_kernel(float* __restrict__ q, float* __restrict__ k,
                          const float* __restrict__ qg, const float* __restrict__ qb,
                          const float* __restrict__ kg, const float* __restrict__ kb)
{
    int warp = (blockIdx.x * blockDim.x + threadIdx.x) >> 5;
    int lane = threadIdx.x & 31;
    const int total = BHv * Nv;     // rows per tensor
    float* buf; const float *g, *bt;
    int r = warp;
    if (r < total) { buf = q; g = qg; bt = qb; }
    else           { r -= total; buf = k; g = kg; bt = kb; }
    float* p = buf + (size_t)r * Dv;
    float x0 = p[lane], x1 = p[lane + 32];
    float s = x0 + x1;
    #pragma unroll
    for (int o = 16; o; o >>= 1) s += __shfl_xor_sync(0xFFFFFFFFu, s, o);
    float mu = s * (1.f/64.f);
    float d0 = x0 - mu, d1 = x1 - mu;
    float v2 = d0*d0 + d1*d1;
    #pragma unroll
    for (int o = 16; o; o >>= 1) v2 += __shfl_xor_sync(0xFFFFFFFFu, v2, o);
    float inv = rsqrtf(v2 * (1.f/64.f) + 1e-5f);
    p[lane]      = d0 * inv * g[lane]      + bt[lane];
    p[lane + 32] = d1 * inv * g[lane + 32] + bt[lane + 32];
}

// ---------------- masked scaled softmax: one block per row of 2048 ----------------
__global__ void __launch_bounds__(256)
softmax_kernel(float* __restrict__ s, const unsigned char* __restrict__ mask)
{
    int row = blockIdx.x;            // [0, BH*Nv)
    int bh  = row >> 11;
    int qi  = row & 2047;
    int b   = bh >> 4;
    float* p = s + (size_t)row * Nv;
    const unsigned char* mrow = mask + ((size_t)b * Nv + qi) * Nv;
    int tid = threadIdx.x;

    float v[8];
    float mx = -FLT_MAX;
    #pragma unroll
    for (int i = 0; i < 8; i++) {
        int c = tid + i * 256;
        float x = p[c] * 0.125f;     // d^{-1/2}
        if (mrow[c]) x = -FLT_MAX;
        v[i] = x;
        mx = fmaxf(mx, x);
    }
    __shared__ float red[8];
    #pragma unroll
    for (int o = 16; o; o >>= 1) mx = fmaxf(mx, __shfl_xor_sync(0xFFFFFFFFu, mx, o));
    if ((tid & 31) == 0) red[tid >> 5] = mx;
    __syncthreads();
    float m2 = red[0];
    #pragma unroll
    for (int i = 1; i < 8; i++) m2 = fmaxf(m2, red[i]);
    __syncthreads();

    float ssum = 0.f;
    #pragma unroll
    for (int i = 0; i < 8; i++) {
        float e = __expf(v[i] - m2);
        v[i] = e;
        ssum += e;
    }
    #pragma unroll
    for (int o = 16; o; o >>= 1) ssum += __shfl_xor_sync(0xFFFFFFFFu, ssum, o);
    if ((tid & 31) == 0) red[tid >> 5] = ssum;
    __syncthreads();
    float tot = 0.f;
    #pragma unroll
    for (int i = 0; i < 8; i++) tot += red[i];
    float rinv = 1.f / tot;
    #pragma unroll
    for (int i = 0; i < 8; i++) {
        int c = tid + i * 256;
        p[c] = v[i] * rinv;
    }
}

// ---------------- launch ----------------
extern "C" void kernel_launch(void* const* d_in, const int* in_sizes, int n_in,
                              void* d_out, int out_size)
{
    const float* x            = (const float*)d_in[0];
    const unsigned char* mask = (const unsigned char*)d_in[1];
    const float* w_qkv        = (const float*)d_in[2];
    const float* w_proj       = (const float*)d_in[3];
    const float* b_proj       = (const float*)d_in[4];
    const float* qg           = (const float*)d_in[5];
    const float* qb           = (const float*)d_in[6];
    const float* kg           = (const float*)d_in[7];
    const float* kb           = (const float*)d_in[8];
    float* out                = (float*)d_out;

    void *pq, *pk, *pv, *ps, *pa;
    cudaGetSymbolAddress(&pq, g_q);
    cudaGetSymbolAddress(&pk, g_k);
    cudaGetSymbolAddress(&pv, g_v);
    cudaGetSymbolAddress(&ps, g_s);
    cudaGetSymbolAddress(&pa, g_attn);
    float* q = (float*)pq; float* k = (float*)pk; float* v = (float*)pv;
    float* s = (float*)ps; float* attn = (float*)pa;

    // 1) QKV projection: [4096,1024] @ [3072,1024]^T, scatter to [b,h,n,d]
    {
        EpiQKV epi{q, k, v};
        dim3 grid(C3/128, MROWS/128, 1);
        gemm_tn<128,128,16,8,8><<<grid, 256>>>(x, w_qkv, MROWS, C3, Cv, 0, 0, epi);
    }
    // 2) LayerNorm q, k (per-head rows of 64)
    {
        int warps = 2 * BHv * Nv;        // 131072
        ln_kernel<<<warps/8, 256>>>(q, k, qg, qb, kg, kb);
    }
    // 3) S = Q @ K^T per (b,h)
    {
        EpiS epi{s};
        dim3 grid(Nv/128, Nv/128, BHv);
        gemm_tn<128,128,16,8,8><<<grid, 256>>>(q, k, Nv, Nv, Dv,
                                               (long long)Nv*Dv, (long long)Nv*Dv, epi);
    }
    // 4) masked scaled softmax over rows of 2048
    softmax_kernel<<<BHv*Nv, 256>>>(s, mask);
    // 5) O = P @ V per (b,h), scatter into [b*n, h*d]
    {
        EpiPV epi{attn};
        dim3 grid(Dv/64, Nv/128, BHv);
        gemm_nn<128,64,16,8,4><<<grid, 256>>>(s, v, Nv, Dv, Nv,
                                              (long long)Nv*Nv, (long long)Nv*Dv, epi);
    }
    // 6) out = attn @ w_proj^T + b_proj
    {
        EpiOut epi{out, b_proj};
        dim3 grid(Cv/128, MROWS/128, 1);
        gemm_tn<128,128,16,8,8><<<grid, 256>>>(attn, w_proj, MROWS, Cv, Cv, 0, 0, epi);
    }
}

// round 2
// speedup vs baseline: 2.5278x; 2.5278x over previous
#include <cuda_runtime.h>
#include <math.h>
#include <float.h>
#include <stdint.h>

// Problem constants
#define Bv 2
#define Nv 2048
#define Cv 1024
#define Hv 16
#define Dv 64
#define BHv (Bv*Hv)        // 32
#define MROWS (Bv*Nv)      // 4096
#define C3 (3*Cv)          // 3072

// Static device scratch (allocation-free rule)
__device__ float g_q[BHv*Nv*Dv];            // 16 MB, [b,h,n,d]
__device__ float g_k[BHv*Nv*Dv];
__device__ float g_v[BHv*Nv*Dv];
__device__ float g_s[(size_t)BHv*Nv*Nv];    // 512 MB scores
__device__ float g_attn[MROWS*Cv];          // 16 MB, [b*n, h*d]

// ---------------- tf32 helpers ----------------
__device__ __forceinline__ float f2tf32(float x) {
    uint32_t u;
    asm("cvt.rna.tf32.f32 %0, %1;" : "=r"(u) : "f"(x));
    return __uint_as_float(u);
}

__device__ __forceinline__ void mma_tf32(float* c, const uint32_t* a, const uint32_t* b) {
    asm volatile(
        "mma.sync.aligned.m16n8k8.row.col.f32.tf32.tf32.f32 "
        "{%0,%1,%2,%3}, {%4,%5,%6,%7}, {%8,%9}, {%0,%1,%2,%3};\n"
        : "+f"(c[0]), "+f"(c[1]), "+f"(c[2]), "+f"(c[3])
        : "r"(a[0]), "r"(a[1]), "r"(a[2]), "r"(a[3]), "r"(b[0]), "r"(b[1]));
}

// ---------------- Epilogue functors ----------------
struct EpiQKV {
    float *q, *k, *v;
    __device__ __forceinline__ void operator()(int bz, int m, int n, float val) const {
        int b   = m >> 11;
        int tok = m & 2047;
        int which = n >> 10;        // 0=q,1=k,2=v
        int h   = (n & 1023) >> 6;
        int dd  = n & 63;
        float* dst = (which == 0) ? q : ((which == 1) ? k : v);
        dst[(((b*Hv + h)*Nv + tok) << 6) + dd] = val;
    }
};

struct EpiS {
    float* s;
    __device__ __forceinline__ void operator()(int bz, int m, int n, float val) const {
        s[((size_t)bz*Nv + m)*Nv + n] = val;
    }
};

struct EpiPV {
    float* attn;
    __device__ __forceinline__ void operator()(int bz, int m, int n, float val) const {
        int b = bz >> 4;
        int h = bz & 15;
        attn[((size_t)(b*Nv + m))*Cv + h*Dv + n] = val;
    }
};

struct EpiOut {
    float* out;
    const float* bias;
    __device__ __forceinline__ void operator()(int bz, int m, int n, float val) const {
        out[(size_t)m*Cv + n] = val + bias[n];
    }
};

// ============ tf32 tensor-core GEMM, TN: C = A(MxK,rm) * B(NxK,rm)^T ============
template<int BM, int BN, int BK, int WM, int WN, class Epi>
__global__ void __launch_bounds__((BM/WM)*(BN/WN)*32)
gemm_tc_tn(const float* __restrict__ A, const float* __restrict__ B,
           int K, long long sA, long long sB, Epi epi)
{
    constexpr int WARPS_M = BM / WM;
    constexpr int WARPS_N = BN / WN;
    constexpr int THREADS = WARPS_M * WARPS_N * 32;
    constexpr int MT = WM / 16;
    constexpr int NT = WN / 8;
    constexpr int PAD = 4;
    constexpr int VPR = BK / 4;          // float4 per row

    __shared__ float As[BM][BK + PAD];
    __shared__ float Bs[BN][BK + PAD];

    const int bz = blockIdx.z;
    A += (long long)bz * sA + (long long)blockIdx.y * BM * K;
    B += (long long)bz * sB + (long long)blockIdx.x * BN * K;
    const int tid  = threadIdx.x;
    const int warp = tid >> 5, lane = tid & 31;
    const int wm = warp / WARPS_N, wn = warp % WARPS_N;
    const int group = lane >> 2, tg = lane & 3;

    float acc[MT][NT][4];
    #pragma unroll
    for (int i = 0; i < MT; i++)
        #pragma unroll
        for (int j = 0; j < NT; j++)
            #pragma unroll
            for (int r = 0; r < 4; r++) acc[i][j][r] = 0.f;

    for (int k0 = 0; k0 < K; k0 += BK) {
        #pragma unroll
        for (int i = tid; i < BM * VPR; i += THREADS) {
            int m = i / VPR, kv = i % VPR;
            float4 t = *(const float4*)(A + (long long)m * K + k0 + kv * 4);
            t.x = f2tf32(t.x); t.y = f2tf32(t.y); t.z = f2tf32(t.z); t.w = f2tf32(t.w);
            *(float4*)&As[m][kv * 4] = t;
        }
        #pragma unroll
        for (int i = tid; i < BN * VPR; i += THREADS) {
            int n = i / VPR, kv = i % VPR;
            float4 t = *(const float4*)(B + (long long)n * K + k0 + kv * 4);
            t.x = f2tf32(t.x); t.y = f2tf32(t.y); t.z = f2tf32(t.z); t.w = f2tf32(t.w);
            *(float4*)&Bs[n][kv * 4] = t;
        }
        __syncthreads();

        #pragma unroll
        for (int kk = 0; kk < BK; kk += 8) {
            uint32_t af[MT][4], bf[NT][2];
            #pragma unroll
            for (int mt = 0; mt < MT; mt++) {
                int r = wm * WM + mt * 16 + group;
                af[mt][0] = __float_as_uint(As[r    ][kk + tg]);
                af[mt][1] = __float_as_uint(As[r + 8][kk + tg]);
                af[mt][2] = __float_as_uint(As[r    ][kk + tg + 4]);
                af[mt][3] = __float_as_uint(As[r + 8][kk + tg + 4]);
            }
            #pragma unroll
            for (int nt = 0; nt < NT; nt++) {
                int c = wn * WN + nt * 8 + group;
                bf[nt][0] = __float_as_uint(Bs[c][kk + tg]);
                bf[nt][1] = __float_as_uint(Bs[c][kk + tg + 4]);
            }
            #pragma unroll
            for (int mt = 0; mt < MT; mt++)
                #pragma unroll
                for (int nt = 0; nt < NT; nt++)
                    mma_tf32(acc[mt][nt], af[mt], bf[nt]);
        }
        __syncthreads();
    }

    const int bm = blockIdx.y * BM, bn = blockIdx.x * BN;
    #pragma unroll
    for (int mt = 0; mt < MT; mt++)
        #pragma unroll
        for (int nt = 0; nt < NT; nt++) {
            int r0 = bm + wm * WM + mt * 16 + group;
            int c0 = bn + wn * WN + nt * 8 + tg * 2;
            epi(bz, r0,     c0,     acc[mt][nt][0]);
            epi(bz, r0,     c0 + 1, acc[mt][nt][1]);
            epi(bz, r0 + 8, c0,     acc[mt][nt][2]);
            epi(bz, r0 + 8, c0 + 1, acc[mt][nt][3]);
        }
}

// ============ tf32 tensor-core GEMM, NN: C = A(MxK,rm) * B(KxN,rm) ============
template<int BM, int BN, int BK, int WM, int WN, class Epi>
__global__ void __launch_bounds__((BM/WM)*(BN/WN)*32)
gemm_tc_nn(const float* __restrict__ A, const float* __restrict__ B,
           int K, int ldb, long long sA, long long sB, Epi epi)
{
    constexpr int WARPS_M = BM / WM;
    constexpr int WARPS_N = BN / WN;
    constexpr int THREADS = WARPS_M * WARPS_N * 32;
    constexpr int MT = WM / 16;
    constexpr int NT = WN / 8;
    constexpr int PAD = 4;
    constexpr int VPRA = BK / 4;
    constexpr int VPRB = BN / 4;

    __shared__ float As[BM][BK + PAD];
    __shared__ float Bs[BK][BN + PAD];

    const int bz = blockIdx.z;
    A += (long long)bz * sA + (long long)blockIdx.y * BM * K;
    B += (long long)bz * sB + blockIdx.x * BN;
    const int tid  = threadIdx.x;
    const int warp = tid >> 5, lane = tid & 31;
    const int wm = warp / WARPS_N, wn = warp % WARPS_N;
    const int group = lane >> 2, tg = lane & 3;

    float acc[MT][NT][4];
    #pragma unroll
    for (int i = 0; i < MT; i++)
        #pragma unroll
        for (int j = 0; j < NT; j++)
            #pragma unroll
            for (int r = 0; r < 4; r++) acc[i][j][r] = 0.f;

    for (int k0 = 0; k0 < K; k0 += BK) {
        #pragma unroll
        for (int i = tid; i < BM * VPRA; i += THREADS) {
            int m = i / VPRA, kv = i % VPRA;
            float4 t = *(const float4*)(A + (long long)m * K + k0 + kv * 4);
            t.x = f2tf32(t.x); t.y = f2tf32(t.y); t.z = f2tf32(t.z); t.w = f2tf32(t.w);
            *(float4*)&As[m][kv * 4] = t;
        }
        #pragma unroll
        for (int i = tid; i < BK * VPRB; i += THREADS) {
            int kk = i / VPRB, nv = i % VPRB;
            float4 t = *(const float4*)(B + (long long)(k0 + kk) * ldb + nv * 4);
            t.x = f2tf32(t.x); t.y = f2tf32(t.y); t.z = f2tf32(t.z); t.w = f2tf32(t.w);
            *(float4*)&Bs[kk][nv * 4] = t;
        }
        __syncthreads();

        #pragma unroll
        for (int kk = 0; kk < BK; kk += 8) {
            uint32_t af[MT][4], bf[NT][2];
            #pragma unroll
            for (int mt = 0; mt < MT; mt++) {
                int r = wm * WM + mt * 16 + group;
                af[mt][0] = __float_as_uint(As[r    ][kk + tg]);
                af[mt][1] = __float_as_uint(As[r + 8][kk + tg]);
                af[mt][2] = __float_as_uint(As[r    ][kk + tg + 4]);
                af[mt][3] = __float_as_uint(As[r + 8][kk + tg + 4]);
            }
            #pragma unroll
            for (int nt = 0; nt < NT; nt++) {
                int c = wn * WN + nt * 8 + group;
                bf[nt][0] = __float_as_uint(Bs[kk + tg    ][c]);
                bf[nt][1] = __float_as_uint(Bs[kk + tg + 4][c]);
            }
            #pragma unroll
            for (int mt = 0; mt < MT; mt++)
                #pragma unroll
                for (int nt = 0; nt < NT; nt++)
                    mma_tf32(acc[mt][nt], af[mt], bf[nt]);
        }
        __syncthreads();
    }

    const int bm = blockIdx.y * BM, bn = blockIdx.x * BN;
    #pragma unroll
    for (int mt = 0; mt < MT; mt++)
        #pragma unroll
        for (int nt = 0; nt < NT; nt++) {
            int r0 = bm + wm * WM + mt * 16 + group;
            int c0 = bn + wn * WN + nt * 8 + tg * 2;
            epi(bz, r0,     c0,     acc[mt][nt][0]);
            epi(bz, r0,     c0 + 1, acc[mt][nt][1]);
            epi(bz, r0 + 8, c0,     acc[mt][nt][2]);
            epi(bz, r0 + 8, c0 + 1, acc[mt][nt][3]);
        }
}

// ---------------- LayerNorm over d=64, one warp per row ----------------
__global__ void ln_kernel(float* __restrict__ q, float* __restrict__ k,
                          const float* __restrict__ qg, const float* __restrict__ qb,
                          const float* __restrict__ kg, const float* __restrict__ kb)
{
    int warp = (blockIdx.x * blockDim.x + threadIdx.x) >> 5;
    int lane = threadIdx.x & 31;
    const int total = BHv * Nv;
    float* buf; const float *g, *bt;
    int r = warp;
    if (r < total) { buf = q; g = qg; bt = qb; }
    else           { r -= total; buf = k; g = kg; bt = kb; }
    float* p = buf + (size_t)r * Dv;
    float x0 = p[lane], x1 = p[lane + 32];
    float s = x0 + x1;
    #pragma unroll
    for (int o = 16; o; o >>= 1) s += __shfl_xor_sync(0xFFFFFFFFu, s, o);
    float mu = s * (1.f/64.f);
    float d0 = x0 - mu, d1 = x1 - mu;
    float v2 = d0*d0 + d1*d1;
    #pragma unroll
    for (int o = 16; o; o >>= 1) v2 += __shfl_xor_sync(0xFFFFFFFFu, v2, o);
    float inv = rsqrtf(v2 * (1.f/64.f) + 1e-5f);
    p[lane]      = d0 * inv * g[lane]      + bt[lane];
    p[lane + 32] = d1 * inv * g[lane + 32] + bt[lane + 32];
}

// ---------------- masked scaled softmax: one block per row of 2048 ----------------
__global__ void __launch_bounds__(256)
softmax_kernel(float* __restrict__ s, const unsigned char* __restrict__ mask)
{
    int row = blockIdx.x;
    int bh  = row >> 11;
    int qi  = row & 2047;
    int b   = bh >> 4;
    float* p = s + (size_t)row * Nv;
    const unsigned char* mrow = mask + ((size_t)b * Nv + qi) * Nv;
    int tid = threadIdx.x;

    float v[8];
    float mx = -FLT_MAX;
    #pragma unroll
    for (int i = 0; i < 8; i++) {
        int c = tid + i * 256;
        float x = p[c] * 0.125f;
        if (mrow[c]) x = -FLT_MAX;
        v[i] = x;
        mx = fmaxf(mx, x);
    }
    __shared__ float red[8];
    #pragma unroll
    for (int o = 16; o; o >>= 1) mx = fmaxf(mx, __shfl_xor_sync(0xFFFFFFFFu, mx, o));
    if ((tid & 31) == 0) red[tid >> 5] = mx;
    __syncthreads();
    float m2 = red[0];
    #pragma unroll
    for (int i = 1; i < 8; i++) m2 = fmaxf(m2, red[i]);
    __syncthreads();

    float ssum = 0.f;
    #pragma unroll
    for (int i = 0; i < 8; i++) {
        float e = __expf(v[i] - m2);
        v[i] = e;
        ssum += e;
    }
    #pragma unroll
    for (int o = 16; o; o >>= 1) ssum += __shfl_xor_sync(0xFFFFFFFFu, ssum, o);
    if ((tid & 31) == 0) red[tid >> 5] = ssum;
    __syncthreads();
    float tot = 0.f;
    #pragma unroll
    for (int i = 0; i < 8; i++) tot += red[i];
    float rinv = 1.f / tot;
    #pragma unroll
    for (int i = 0; i < 8; i++) {
        int c = tid + i * 256;
        p[c] = v[i] * rinv;
    }
}

// ---------------- launch ----------------
extern "C" void kernel_launch(void* const* d_in, const int* in_sizes, int n_in,
                              void* d_out, int out_size)
{
    const float* x            = (const float*)d_in[0];
    const unsigned char* mask = (const unsigned char*)d_in[1];
    const float* w_qkv        = (const float*)d_in[2];
    const float* w_proj       = (const float*)d_in[3];
    const float* b_proj       = (const float*)d_in[4];
    const float* qg           = (const float*)d_in[5];
    const float* qb           = (const float*)d_in[6];
    const float* kg           = (const float*)d_in[7];
    const float* kb           = (const float*)d_in[8];
    float* out                = (float*)d_out;

    void *pq, *pk, *pv, *ps, *pa;
    cudaGetSymbolAddress(&pq, g_q);
    cudaGetSymbolAddress(&pk, g_k);
    cudaGetSymbolAddress(&pv, g_v);
    cudaGetSymbolAddress(&ps, g_s);
    cudaGetSymbolAddress(&pa, g_attn);
    float* q = (float*)pq; float* k = (float*)pk; float* v = (float*)pv;
    float* s = (float*)ps; float* attn = (float*)pa;

    // 1) QKV projection: [4096,1024] @ [3072,1024]^T, scatter to [b,h,n,d]
    {
        EpiQKV epi{q, k, v};
        dim3 grid(C3/128, MROWS/128, 1);
        gemm_tc_tn<128,128,32,32,64><<<grid, 256>>>(x, w_qkv, Cv, 0, 0, epi);
    }
    // 2) LayerNorm q, k (per-head rows of 64)
    {
        int warps = 2 * BHv * Nv;
        ln_kernel<<<warps/8, 256>>>(q, k, qg, qb, kg, kb);
    }
    // 3) S = Q @ K^T per (b,h)
    {
        EpiS epi{s};
        dim3 grid(Nv/128, Nv/128, BHv);
        gemm_tc_tn<128,128,32,32,64><<<grid, 256>>>(q, k, Dv,
                                                    (long long)Nv*Dv, (long long)Nv*Dv, epi);
    }
    // 4) masked scaled softmax over rows of 2048
    softmax_kernel<<<BHv*Nv, 256>>>(s, mask);
    // 5) O = P @ V per (b,h), scatter into [b*n, h*d]
    {
        EpiPV epi{attn};
        dim3 grid(1, Nv/128, BHv);
        gemm_tc_nn<128,64,32,32,32><<<grid, 256>>>(s, v, Nv, Dv,
                                                   (long long)Nv*Nv, (long long)Nv*Dv, epi);
    }
    // 6) out = attn @ w_proj^T + b_proj
    {
        EpiOut epi{out, b_proj};
        dim3 grid(Cv/128, MROWS/128, 1);
        gemm_tc_tn<128,128,32,32,64><<<grid, 256>>>(attn, w_proj, Cv, 0, 0, epi);
    }
}

// round 4
// speedup vs baseline: 4.0463x; 1.6007x over previous
#include <cuda_runtime.h>
#include <math.h>
#include <float.h>
#include <stdint.h>

// Problem constants
#define Bv 2
#define Nv 2048
#define Cv 1024
#define Hv 16
#define Dv 64
#define BHv (Bv*Hv)        // 32
#define MROWS (Bv*Nv)      // 4096
#define C3 (3*Cv)          // 3072

// Static device scratch (allocation-free rule)
__device__ float g_q[BHv*Nv*Dv];            // 16 MB, [b,h,n,d]
__device__ float g_k[BHv*Nv*Dv];
__device__ float g_v[BHv*Nv*Dv];
__device__ float g_attn[MROWS*Cv];          // 16 MB, [b*n, h*d]
__device__ int   g_maskflag;

// ---------------- tf32 helpers ----------------
__device__ __forceinline__ float f2tf32(float x) {
    uint32_t u;
    asm("cvt.rna.tf32.f32 %0, %1;" : "=r"(u) : "f"(x));
    return __uint_as_float(u);
}

__device__ __forceinline__ void mma_tf32(float* c, const uint32_t* a, uint32_t b0, uint32_t b1) {
    asm volatile(
        "mma.sync.aligned.m16n8k8.row.col.f32.tf32.tf32.f32 "
        "{%0,%1,%2,%3}, {%4,%5,%6,%7}, {%8,%9}, {%0,%1,%2,%3};\n"
        : "+f"(c[0]), "+f"(c[1]), "+f"(c[2]), "+f"(c[3])
        : "r"(a[0]), "r"(a[1]), "r"(a[2]), "r"(a[3]), "r"(b0), "r"(b1));
}

__device__ __forceinline__ void cp16(uint32_t dst, const void* src) {
    asm volatile("cp.async.cg.shared.global [%0], [%1], 16;\n" :: "r"(dst), "l"(src));
}

// ---------------- Epilogue functors ----------------
struct EpiQKV {
    float *q, *k, *v;
    __device__ __forceinline__ void operator()(int bz, int m, int n, float val) const {
        int b   = m >> 11;
        int tok = m & 2047;
        int which = n >> 10;        // 0=q,1=k,2=v
        int h   = (n & 1023) >> 6;
        int dd  = n & 63;
        if (which == 2) val = f2tf32(val);   // V used directly by attention mma
        float* dst = (which == 0) ? q : ((which == 1) ? k : v);
        dst[(((b*Hv + h)*Nv + tok) << 6) + dd] = val;
    }
};

struct EpiOut {
    float* out;
    const float* bias;
    __device__ __forceinline__ void operator()(int bz, int m, int n, float val) const {
        out[(size_t)m*Cv + n] = val + bias[n];
    }
};

// ============ tf32 tensor-core GEMM, TN: C = A(MxK,rm) * B(NxK,rm)^T ============
template<int BM, int BN, int BK, int WM, int WN, class Epi>
__global__ void __launch_bounds__((BM/WM)*(BN/WN)*32)
gemm_tc_tn(const float* __restrict__ A, const float* __restrict__ B,
           int K, long long sA, long long sB, Epi epi)
{
    constexpr int WARPS_M = BM / WM;
    constexpr int WARPS_N = BN / WN;
    constexpr int THREADS = WARPS_M * WARPS_N * 32;
    constexpr int MT = WM / 16;
    constexpr int NT = WN / 8;
    constexpr int PAD = 4;
    constexpr int VPR = BK / 4;

    __shared__ float As[BM][BK + PAD];
    __shared__ float Bs[BN][BK + PAD];

    const int bz = blockIdx.z;
    A += (long long)bz * sA + (long long)blockIdx.y * BM * K;
    B += (long long)bz * sB + (long long)blockIdx.x * BN * K;
    const int tid  = threadIdx.x;
    const int warp = tid >> 5, lane = tid & 31;
    const int wm = warp / WARPS_N, wn = warp % WARPS_N;
    const int group = lane >> 2, tg = lane & 3;

    float acc[MT][NT][4];
    #pragma unroll
    for (int i = 0; i < MT; i++)
        #pragma unroll
        for (int j = 0; j < NT; j++)
            #pragma unroll
            for (int r = 0; r < 4; r++) acc[i][j][r] = 0.f;

    for (int k0 = 0; k0 < K; k0 += BK) {
        #pragma unroll
        for (int i = tid; i < BM * VPR; i += THREADS) {
            int m = i / VPR, kv = i % VPR;
            float4 t = *(const float4*)(A + (long long)m * K + k0 + kv * 4);
            t.x = f2tf32(t.x); t.y = f2tf32(t.y); t.z = f2tf32(t.z); t.w = f2tf32(t.w);
            *(float4*)&As[m][kv * 4] = t;
        }
        #pragma unroll
        for (int i = tid; i < BN * VPR; i += THREADS) {
            int n = i / VPR, kv = i % VPR;
            float4 t = *(const float4*)(B + (long long)n * K + k0 + kv * 4);
            t.x = f2tf32(t.x); t.y = f2tf32(t.y); t.z = f2tf32(t.z); t.w = f2tf32(t.w);
            *(float4*)&Bs[n][kv * 4] = t;
        }
        __syncthreads();

        #pragma unroll
        for (int kk = 0; kk < BK; kk += 8) {
            uint32_t af[MT][4], bf[NT][2];
            #pragma unroll
            for (int mt = 0; mt < MT; mt++) {
                int r = wm * WM + mt * 16 + group;
                af[mt][0] = __float_as_uint(As[r    ][kk + tg]);
                af[mt][1] = __float_as_uint(As[r + 8][kk + tg]);
                af[mt][2] = __float_as_uint(As[r    ][kk + tg + 4]);
                af[mt][3] = __float_as_uint(As[r + 8][kk + tg + 4]);
            }
            #pragma unroll
            for (int nt = 0; nt < NT; nt++) {
                int c = wn * WN + nt * 8 + group;
                bf[nt][0] = __float_as_uint(Bs[c][kk + tg]);
                bf[nt][1] = __float_as_uint(Bs[c][kk + tg + 4]);
            }
            #pragma unroll
            for (int mt = 0; mt < MT; mt++)
                #pragma unroll
                for (int nt = 0; nt < NT; nt++)
                    mma_tf32(acc[mt][nt], af[mt], bf[nt][0], bf[nt][1]);
        }
        __syncthreads();
    }

    const int bm = blockIdx.y * BM, bn = blockIdx.x * BN;
    #pragma unroll
    for (int mt = 0; mt < MT; mt++)
        #pragma unroll
        for (int nt = 0; nt < NT; nt++) {
            int r0 = bm + wm * WM + mt * 16 + group;
            int c0 = bn + wn * WN + nt * 8 + tg * 2;
            epi(bz, r0,     c0,     acc[mt][nt][0]);
            epi(bz, r0,     c0 + 1, acc[mt][nt][1]);
            epi(bz, r0 + 8, c0,     acc[mt][nt][2]);
            epi(bz, r0 + 8, c0 + 1, acc[mt][nt][3]);
        }
}

// ---------------- LayerNorm over d=64, one warp per row; tf32-round outputs ----------------
__global__ void ln_kernel(float* __restrict__ q, float* __restrict__ k,
                          const float* __restrict__ qg, const float* __restrict__ qb,
                          const float* __restrict__ kg, const float* __restrict__ kb)
{
    int warp = (blockIdx.x * blockDim.x + threadIdx.x) >> 5;
    int lane = threadIdx.x & 31;
    const int total = BHv * Nv;
    float* buf; const float *g, *bt;
    int r = warp;
    if (r < total) { buf = q; g = qg; bt = qb; }
    else           { r -= total; buf = k; g = kg; bt = kb; }
    float* p = buf + (size_t)r * Dv;
    float x0 = p[lane], x1 = p[lane + 32];
    float s = x0 + x1;
    #pragma unroll
    for (int o = 16; o; o >>= 1) s += __shfl_xor_sync(0xFFFFFFFFu, s, o);
    float mu = s * (1.f/64.f);
    float d0 = x0 - mu, d1 = x1 - mu;
    float v2 = d0*d0 + d1*d1;
    #pragma unroll
    for (int o = 16; o; o >>= 1) v2 += __shfl_xor_sync(0xFFFFFFFFu, v2, o);
    float inv = rsqrtf(v2 * (1.f/64.f) + 1e-5f);
    p[lane]      = f2tf32(d0 * inv * g[lane]      + bt[lane]);
    p[lane + 32] = f2tf32(d1 * inv * g[lane + 32] + bt[lane + 32]);
}

// ---------------- mask any-true scan ----------------
__global__ void mask_any_kernel(const uint4* __restrict__ m, int n4, int* flag)
{
    int i = blockIdx.x * blockDim.x + threadIdx.x;
    bool any = false;
    for (; i < n4; i += gridDim.x * blockDim.x) {
        uint4 t = m[i];
        any |= ((t.x | t.y | t.z | t.w) != 0u);
    }
    if (__syncthreads_or(any)) {
        if (threadIdx.x == 0) atomicOr(flag, 1);
    }
}

// ================= fused flash attention =================
// grid: (16 q-tiles, 32 bh). block: 256 threads (8 warps, 16 q-rows each).
// S tile 128x128 per CTA, kv loop of 16 tiles, online softmax, tf32 mma.
#define FP 68               // padded smem row pitch (floats)
#define TILEF (128*FP)      // floats per smem tile buffer

__global__ void __launch_bounds__(256, 1)
flash_kernel(const float* __restrict__ q, const float* __restrict__ k,
             const float* __restrict__ v, const unsigned char* __restrict__ mask,
             const int* __restrict__ maskflag, float* __restrict__ aout)
{
    extern __shared__ float sm[];            // [K0][K1][V0][V1], each 128*FP floats
    const int tid  = threadIdx.x;
    const int warp = tid >> 5, lane = tid & 31;
    const int group = lane >> 2, tg = lane & 3;
    const int qtile = blockIdx.x;
    const int bh = blockIdx.y;
    const int bB = bh >> 4, h = bh & 15;
    const int mf = *maskflag;

    const float* qbase = q + (size_t)bh * Nv * Dv + (size_t)qtile * 128 * Dv;
    const float* kbase = k + (size_t)bh * Nv * Dv;
    const float* vbase = v + (size_t)bh * Nv * Dv;
    uint32_t sbase = (uint32_t)__cvta_generic_to_shared(sm);

    // ---- stage Q tile into sm[0..TILEF), pre-scaled by d^-1/2 (exact pow2) ----
    #pragma unroll
    for (int i = 0; i < 8; i++) {
        int idx = tid + i * 256;
        int row = idx >> 4, c4 = (idx & 15) * 4;
        float4 t = *(const float4*)(qbase + row * Dv + c4);
        t.x *= 0.125f; t.y *= 0.125f; t.z *= 0.125f; t.w *= 0.125f;
        *(float4*)(sm + row * FP + c4) = t;
    }
    __syncthreads();

    // read Q fragments to registers (rows warp*16+group, warp*16+group+8)
    uint32_t qf[8][4];
    {
        const float* Qr = sm + (warp * 16 + group) * FP;
        #pragma unroll
        for (int kk = 0; kk < 8; kk++) {
            qf[kk][0] = __float_as_uint(Qr[kk*8 + tg]);
            qf[kk][1] = __float_as_uint(Qr[8*FP + kk*8 + tg]);
            qf[kk][2] = __float_as_uint(Qr[kk*8 + tg + 4]);
            qf[kk][3] = __float_as_uint(Qr[8*FP + kk*8 + tg + 4]);
        }
    }
    __syncthreads();

    // ---- prefetch helper: K/V tile t into buffer b ----
    auto prefetch = [&](int t, int b) {
        const float* kb = kbase + (size_t)t * 128 * Dv;
        const float* vb = vbase + (size_t)t * 128 * Dv;
        uint32_t kd = sbase + (uint32_t)(b * TILEF) * 4u;
        uint32_t vd = sbase + (uint32_t)((2 + b) * TILEF) * 4u;
        #pragma unroll
        for (int i = 0; i < 8; i++) {
            int idx = tid + i * 256;
            int row = idx >> 4, c4 = (idx & 15) * 4;
            cp16(kd + (row * FP + c4) * 4, kb + row * Dv + c4);
            cp16(vd + (row * FP + c4) * 4, vb + row * Dv + c4);
        }
        asm volatile("cp.async.commit_group;\n" ::: "memory");
    };

    prefetch(0, 0);
    prefetch(1, 1);

    // ---- running state ----
    float m0 = -FLT_MAX, m1 = -FLT_MAX, l0 = 0.f, l1 = 0.f;
    float oacc[8][4];
    #pragma unroll
    for (int i = 0; i < 8; i++)
        #pragma unroll
        for (int j = 0; j < 4; j++) oacc[i][j] = 0.f;

    const int qb4 = lane & ~3;

    for (int t = 0; t < 16; t++) {
        const int buf = t & 1;
        if (t < 15) asm volatile("cp.async.wait_group 1;\n" ::: "memory");
        else        asm volatile("cp.async.wait_group 0;\n" ::: "memory");
        __syncthreads();

        const float* Kb = sm + buf * TILEF;
        const float* Vb = sm + (2 + buf) * TILEF;

        // ---- S = Q K^T (tile 16x128 per warp) ----
        float sacc[16][4];
        #pragma unroll
        for (int nt = 0; nt < 16; nt++)
            #pragma unroll
            for (int r = 0; r < 4; r++) sacc[nt][r] = 0.f;

        #pragma unroll
        for (int kk = 0; kk < 8; kk++) {
            #pragma unroll
            for (int nt = 0; nt < 16; nt++) {
                const float* Kr = Kb + (nt * 8 + group) * FP + kk * 8;
                uint32_t b0 = __float_as_uint(Kr[tg]);
                uint32_t b1 = __float_as_uint(Kr[tg + 4]);
                mma_tf32(sacc[nt], qf[kk], b0, b1);
            }
        }

        // ---- mask (rare path; fast path skips entirely) ----
        if (mf) {
            const unsigned char* mr0 = mask + ((size_t)(bB * Nv + qtile*128 + warp*16 + group)) * Nv + t * 128;
            const unsigned char* mr1 = mr0 + 8 * Nv;
            #pragma unroll
            for (int nt = 0; nt < 16; nt++) {
                int c = nt * 8 + 2 * tg;
                if (mr0[c])     sacc[nt][0] = -FLT_MAX;
                if (mr0[c + 1]) sacc[nt][1] = -FLT_MAX;
                if (mr1[c])     sacc[nt][2] = -FLT_MAX;
                if (mr1[c + 1]) sacc[nt][3] = -FLT_MAX;
            }
        }

        // ---- online softmax ----
        float mn0 = -FLT_MAX, mn1 = -FLT_MAX;
        #pragma unroll
        for (int nt = 0; nt < 16; nt++) {
            mn0 = fmaxf(mn0, fmaxf(sacc[nt][0], sacc[nt][1]));
            mn1 = fmaxf(mn1, fmaxf(sacc[nt][2], sacc[nt][3]));
        }
        mn0 = fmaxf(mn0, __shfl_xor_sync(0xFFFFFFFFu, mn0, 1));
        mn0 = fmaxf(mn0, __shfl_xor_sync(0xFFFFFFFFu, mn0, 2));
        mn1 = fmaxf(mn1, __shfl_xor_sync(0xFFFFFFFFu, mn1, 1));
        mn1 = fmaxf(mn1, __shfl_xor_sync(0xFFFFFFFFu, mn1, 2));

        float mt0 = fmaxf(m0, mn0), mt1 = fmaxf(m1, mn1);
        float a0 = __expf(m0 - mt0), a1 = __expf(m1 - mt1);
        float rs0 = 0.f, rs1 = 0.f;
        #pragma unroll
        for (int nt = 0; nt < 16; nt++) {
            float p0 = __expf(sacc[nt][0] - mt0);
            float p1 = __expf(sacc[nt][1] - mt0);
            float p2 = __expf(sacc[nt][2] - mt1);
            float p3 = __expf(sacc[nt][3] - mt1);
            rs0 += p0 + p1; rs1 += p2 + p3;
            sacc[nt][0] = f2tf32(p0); sacc[nt][1] = f2tf32(p1);
            sacc[nt][2] = f2tf32(p2); sacc[nt][3] = f2tf32(p3);
        }
        rs0 += __shfl_xor_sync(0xFFFFFFFFu, rs0, 1);
        rs0 += __shfl_xor_sync(0xFFFFFFFFu, rs0, 2);
        rs1 += __shfl_xor_sync(0xFFFFFFFFu, rs1, 1);
        rs1 += __shfl_xor_sync(0xFFFFFFFFu, rs1, 2);
        l0 = a0 * l0 + rs0;
        l1 = a1 * l1 + rs1;
        m0 = mt0; m1 = mt1;
        #pragma unroll
        for (int i = 0; i < 8; i++) {
            oacc[i][0] *= a0; oacc[i][1] *= a0;
            oacc[i][2] *= a1; oacc[i][3] *= a1;
        }

        // ---- O += P V ----
        #pragma unroll
        for (int kc = 0; kc < 16; kc++) {
            int srcA = qb4 + (tg >> 1);
            int srcB = srcA + 2;
            float v0 = __shfl_sync(0xFFFFFFFFu, sacc[kc][0], srcA);
            float v1 = __shfl_sync(0xFFFFFFFFu, sacc[kc][1], srcA);
            float v2 = __shfl_sync(0xFFFFFFFFu, sacc[kc][0], srcB);
            float v3 = __shfl_sync(0xFFFFFFFFu, sacc[kc][1], srcB);
            float w0 = __shfl_sync(0xFFFFFFFFu, sacc[kc][2], srcA);
            float w1 = __shfl_sync(0xFFFFFFFFu, sacc[kc][3], srcA);
            float w2 = __shfl_sync(0xFFFFFFFFu, sacc[kc][2], srcB);
            float w3 = __shfl_sync(0xFFFFFFFFu, sacc[kc][3], srcB);
            uint32_t a[4];
            bool odd = (tg & 1);
            a[0] = __float_as_uint(odd ? v1 : v0);
            a[1] = __float_as_uint(odd ? w1 : w0);
            a[2] = __float_as_uint(odd ? v3 : v2);
            a[3] = __float_as_uint(odd ? w3 : w2);
            #pragma unroll
            for (int nt = 0; nt < 8; nt++) {
                const float* Vr = Vb + (kc * 8 + tg) * FP + nt * 8 + group;
                uint32_t b0 = __float_as_uint(Vr[0]);
                uint32_t b1 = __float_as_uint(Vr[4 * FP]);
                mma_tf32(oacc[nt], a, b0, b1);
            }
        }

        __syncthreads();
        if (t + 2 < 16) prefetch(t + 2, buf);
    }

    // ---- finalize: O /= l, write to [b*N+token][h*64+col] ----
    float inv0 = 1.f / l0, inv1 = 1.f / l1;
    int tok0 = qtile * 128 + warp * 16 + group;
    float* or0 = aout + ((size_t)(bB * Nv + tok0)) * Cv + h * Dv;
    float* or1 = or0 + 8 * (size_t)Cv;
    #pragma unroll
    for (int nt = 0; nt < 8; nt++) {
        int c = nt * 8 + 2 * tg;
        *(float2*)(or0 + c) = make_float2(oacc[nt][0] * inv0, oacc[nt][1] * inv0);
        *(float2*)(or1 + c) = make_float2(oacc[nt][2] * inv1, oacc[nt][3] * inv1);
    }
}

// ---------------- launch ----------------
extern "C" void kernel_launch(void* const* d_in, const int* in_sizes, int n_in,
                              void* d_out, int out_size)
{
    const float* x            = (const float*)d_in[0];
    const unsigned char* mask = (const unsigned char*)d_in[1];
    const float* w_qkv        = (const float*)d_in[2];
    const float* w_proj       = (const float*)d_in[3];
    const float* b_proj       = (const float*)d_in[4];
    const float* qg           = (const float*)d_in[5];
    const float* qb           = (const float*)d_in[6];
    const float* kg           = (const float*)d_in[7];
    const float* kb           = (const float*)d_in[8];
    float* out                = (float*)d_out;

    void *pq, *pk, *pv, *pa, *pf;
    cudaGetSymbolAddress(&pq, g_q);
    cudaGetSymbolAddress(&pk, g_k);
    cudaGetSymbolAddress(&pv, g_v);
    cudaGetSymbolAddress(&pa, g_attn);
    cudaGetSymbolAddress(&pf, g_maskflag);
    float* q = (float*)pq; float* k = (float*)pk; float* v = (float*)pv;
    float* attn = (float*)pa; int* flag = (int*)pf;

    const int FLASH_SMEM = 4 * TILEF * 4;   // 139264 bytes
    cudaFuncSetAttribute(flash_kernel, cudaFuncAttributeMaxDynamicSharedMemorySize, FLASH_SMEM);

    // 0) mask any-true flag
    cudaMemsetAsync(flag, 0, sizeof(int));
    mask_any_kernel<<<512, 256>>>((const uint4*)mask, (Bv*Nv*Nv)/16, flag);

    // 1) QKV projection: [4096,1024] @ [3072,1024]^T -> q/k/v [b,h,n,d]
    {
        EpiQKV epi{q, k, v};
        dim3 grid(C3/128, MROWS/128, 1);
        gemm_tc_tn<128,128,32,32,64><<<grid, 256>>>(x, w_qkv, Cv, 0, 0, epi);
    }
    // 2) LayerNorm q, k (per-head rows of 64), tf32-rounded outputs
    {
        int warps = 2 * BHv * Nv;
        ln_kernel<<<warps/8, 256>>>(q, k, qg, qb, kg, kb);
    }
    // 3) fused attention: softmax(QK^T * scale + mask) V -> g_attn
    {
        dim3 grid(Nv/128, BHv);
        flash_kernel<<<grid, 256, FLASH_SMEM>>>(q, k, v, mask, flag, attn);
    }
    // 4) out = attn @ w_proj^T + b_proj
    {
        EpiOut epi{out, b_proj};
        dim3 grid(Cv/128, MROWS/128, 1);
        gemm_tc_tn<128,128,32,32,64><<<grid, 256>>>(attn, w_proj, Cv, 0, 0, epi);
    }
}